// round 14
// baseline (speedup 1.0000x reference)
#include <cuda_runtime.h>
#include <cuda_bf16.h>
#include <cuda_fp16.h>
#include <cstdint>

#define N_NODES 100000
#define N_EDGES 1600000
#define N_GRAPHS 512
#define CAP 64
#define OVF_CAP 8192

// -------- persistent device state (self-cleaning across calls; .bss zero) --
__device__ int     g_cnt[N_NODES];          // zeroed by agg2 of previous call
__device__ int     g_col[N_NODES * CAP];
__device__ float   g_dinv[N_NODES];
__device__ __half2 g_tmp_h[N_NODES * 32];   // gemm rows, prescaled by dinv[row]
__device__ __half2 g_h_h[N_NODES * 32];     // layer-1 agg output (+b1), fp16
__device__ float   g_pool[N_GRAPHS * 64];   // zeroed by k_head
__device__ int     g_gcnt[N_GRAPHS];        // zeroed by k_head
__device__ int     g_novf;                  // zeroed by k_head
__device__ int2    g_ovf[OVF_CAP];

__device__ __forceinline__ void cp_async16(uint32_t daddr, const void* src, int nbytes) {
    asm volatile("cp.async.ca.shared.global [%0], [%1], 16, %2;"
                 :: "r"(daddr), "l"(src), "r"(nbytes));
}

// -------- build ELL adjacency; 4 edges per thread --------
__global__ void k_build(const int* __restrict__ ei) {
    int i4 = blockIdx.x * blockDim.x + threadIdx.x;
    if (i4 >= N_EDGES / 4) return;
    int4 s4 = ((const int4*)ei)[i4];
    int4 d4 = ((const int4*)(ei + N_EDGES))[i4];
    int ss[4] = {s4.x, s4.y, s4.z, s4.w};
    int dd[4] = {d4.x, d4.y, d4.z, d4.w};
    #pragma unroll
    for (int k = 0; k < 4; k++) {
        int src = ss[k], dst = dd[k];
        if ((unsigned)src >= N_NODES || (unsigned)dst >= N_NODES) continue;
        int pos = atomicAdd(&g_cnt[dst], 1);
        if (pos < CAP) {
            g_col[dst * CAP + pos] = src;
        } else {
            int o = atomicAdd(&g_novf, 1);
            if (o < OVF_CAP) g_ovf[o] = make_int2(src, dst);
        }
    }
}

__global__ void k_dinv(const int* __restrict__ batch) {
    int i = blockIdx.x * blockDim.x + threadIdx.x;
    if (i >= N_NODES) return;
    g_dinv[i] = rsqrtf((float)(g_cnt[i] + 1));
    int g = batch[i];
    if ((unsigned)g < N_GRAPHS) atomicAdd(&g_gcnt[g], 1);
}

// -------- tensor-core GEMM, persistent + double-buffered cp.async ----------
// Both layers write rows prescaled by dinv[row] (dinv ready before gemm0).
// FROM_H=false: fp32 X @ W1.  FROM_H=true: relu(g_h_h fp16) @ W2.
template <bool FROM_H>
__global__ void __launch_bounds__(256) k_gemm(const float* __restrict__ X,
                                              const float* __restrict__ W) {
    constexpr int PADH = 80;
    constexpr int PADF = 72;
    constexpr int XBYTES = FROM_H ? (128 * PADH * 2) : (128 * PADF * 4);
    extern __shared__ __align__(16) unsigned char smem[];
    unsigned char* xb0 = smem;
    unsigned char* xb1 = smem + XBYTES;
    __half* Wt = (__half*)(smem + 2 * XBYTES);   // Wt[n][k] = W[k][n], 64x72

    int t = threadIdx.x;
    int lane = t & 31;
    int w = t >> 5;
    const int nt = (N_NODES + 127) / 128;

    auto stage = [&](int tile, unsigned char* buf) {
        uint32_t b = (uint32_t)__cvta_generic_to_shared(buf);
        int row0 = tile * 128;
        if (FROM_H) {
            #pragma unroll 4
            for (int i = t; i < 128 * 8; i += 256) {
                int r = i >> 3, ch = i & 7;
                int row = row0 + r;
                int rc = row < N_NODES ? row : 0;
                cp_async16(b + (uint32_t)(r * PADH + ch * 8) * 2,
                           (const char*)g_h_h + (size_t)rc * 128 + ch * 16,
                           row < N_NODES ? 16 : 0);
            }
        } else {
            #pragma unroll 8
            for (int i = t; i < 128 * 16; i += 256) {
                int r = i >> 4, ch = i & 15;
                int row = row0 + r;
                int rc = row < N_NODES ? row : 0;
                cp_async16(b + (uint32_t)(r * PADF + ch * 4) * 4,
                           (const char*)X + (size_t)rc * 256 + ch * 16,
                           row < N_NODES ? 16 : 0);
            }
        }
    };

    int tile = blockIdx.x;
    if (tile < nt) stage(tile, xb0);
    for (int i = t; i < 64 * 64; i += 256) {
        int k = i >> 6, n = i & 63;
        Wt[n * 72 + k] = __float2half_rn(W[i]);
    }
    asm volatile("cp.async.commit_group;");

    int grp = lane >> 2;
    int qid = lane & 3;
    int arow = w * 16 + grp;
    const __half2 z2 = __float2half2_rn(0.f);

    int buf = 0;
    for (; tile < nt; tile += gridDim.x) {
        int nxt = tile + gridDim.x;
        if (nxt < nt) {
            stage(nxt, buf ? xb0 : xb1);
            asm volatile("cp.async.commit_group;");
            asm volatile("cp.async.wait_group 1;");
        } else {
            asm volatile("cp.async.wait_group 0;");
        }
        __syncthreads();

        const unsigned char* xcur = buf ? xb1 : xb0;
        const __half* Xh = (const __half*)xcur;
        const float*  Xf = (const float*)xcur;

        float c[8][4];
        #pragma unroll
        for (int n = 0; n < 8; n++)
            #pragma unroll
            for (int j = 0; j < 4; j++) c[n][j] = 0.f;

        #pragma unroll
        for (int kk = 0; kk < 4; kk++) {
            int k0 = kk * 16 + qid * 2;
            uint32_t a0, a1, a2, a3;
            if (FROM_H) {
                __half2 v0 = __hmax2(*(const __half2*)&Xh[(arow)     * PADH + k0], z2);
                __half2 v1 = __hmax2(*(const __half2*)&Xh[(arow + 8) * PADH + k0], z2);
                __half2 v2 = __hmax2(*(const __half2*)&Xh[(arow)     * PADH + k0 + 8], z2);
                __half2 v3 = __hmax2(*(const __half2*)&Xh[(arow + 8) * PADH + k0 + 8], z2);
                a0 = *reinterpret_cast<uint32_t*>(&v0);
                a1 = *reinterpret_cast<uint32_t*>(&v1);
                a2 = *reinterpret_cast<uint32_t*>(&v2);
                a3 = *reinterpret_cast<uint32_t*>(&v3);
            } else {
                float2 f0 = *(const float2*)&Xf[(arow)     * PADF + k0];
                float2 f1 = *(const float2*)&Xf[(arow + 8) * PADF + k0];
                float2 f2 = *(const float2*)&Xf[(arow)     * PADF + k0 + 8];
                float2 f3 = *(const float2*)&Xf[(arow + 8) * PADF + k0 + 8];
                __half2 v0 = __floats2half2_rn(f0.x, f0.y);
                __half2 v1 = __floats2half2_rn(f1.x, f1.y);
                __half2 v2 = __floats2half2_rn(f2.x, f2.y);
                __half2 v3 = __floats2half2_rn(f3.x, f3.y);
                a0 = *reinterpret_cast<uint32_t*>(&v0);
                a1 = *reinterpret_cast<uint32_t*>(&v1);
                a2 = *reinterpret_cast<uint32_t*>(&v2);
                a3 = *reinterpret_cast<uint32_t*>(&v3);
            }
            #pragma unroll
            for (int n = 0; n < 8; n++) {
                int nc = n * 8 + grp;
                uint32_t b0 = *(const uint32_t*)&Wt[nc * 72 + k0];
                uint32_t b1 = *(const uint32_t*)&Wt[nc * 72 + k0 + 8];
                asm volatile(
                    "mma.sync.aligned.m16n8k16.row.col.f32.f16.f16.f32 "
                    "{%0,%1,%2,%3}, {%4,%5,%6,%7}, {%8,%9}, {%0,%1,%2,%3};"
                    : "+f"(c[n][0]), "+f"(c[n][1]), "+f"(c[n][2]), "+f"(c[n][3])
                    : "r"(a0), "r"(a1), "r"(a2), "r"(a3), "r"(b0), "r"(b1));
            }
        }

        int r0 = tile * 128 + w * 16 + grp;
        int r1 = r0 + 8;
        float dv0 = (r0 < N_NODES) ? g_dinv[r0] : 0.f;
        float dv1 = (r1 < N_NODES) ? g_dinv[r1] : 0.f;
        #pragma unroll
        for (int n = 0; n < 8; n++) {
            int cw = n * 4 + qid;
            if (r0 < N_NODES)
                g_tmp_h[r0 * 32 + cw] = __floats2half2_rn(c[n][0] * dv0, c[n][1] * dv0);
            if (r1 < N_NODES)
                g_tmp_h[r1 * 32 + cw] = __floats2half2_rn(c[n][2] * dv1, c[n][3] * dv1);
        }
        __syncthreads();
        buf ^= 1;
    }
}

// -------- aggregation: warp per node, half-warp edge pairing --------------
// Lanes 0-15 gather edge j (8B/lane = 4 dims), lanes 16-31 edge j+1;
// one variable-index shuffle broadcasts both ids. acc = float4 (4 dims/lane),
// folded across halves with shfl_xor(16) at the end.
template <bool TO_POOL>
__global__ void __launch_bounds__(256) k_agg(const float* __restrict__ bias,
                                             const int* __restrict__ batch) {
    const unsigned F = 0xffffffffu;
    int warp = (blockIdx.x * blockDim.x + threadIdx.x) >> 5;
    int lane = threadIdx.x & 31;
    if (warp >= N_NODES) return;
    int v = warp;
    int half = lane >> 4;    // 0 or 1
    int hl = lane & 15;      // 0..15
    float dv = g_dinv[v];

    const uint2* rows = (const uint2*)g_tmp_h;   // 16 x uint2 per 128B row

    float4 acc = make_float4(0.f, 0.f, 0.f, 0.f);
    auto addrow = [&](uint2 r) {
        __half2 h0 = *reinterpret_cast<__half2*>(&r.x);
        __half2 h1 = *reinterpret_cast<__half2*>(&r.y);
        float2 a = __half22float2(h0);
        float2 b = __half22float2(h1);
        acc.x += a.x; acc.y += a.y; acc.z += b.x; acc.w += b.y;
    };

    if (half == 0) addrow(rows[v * 16 + hl]);    // self term (prescaled)

    int deg = g_cnt[v];
    int degc = deg > CAP ? CAP : deg;
    const int* cols = &g_col[v * CAP];
    for (int base = 0; base < degc; base += 32) {
        int s = (base + lane < degc) ? cols[base + lane] : 0;
        int m = min(32, degc - base);
        int j = 0;
        for (; j + 8 <= m; j += 8) {             // 4 edge-pairs
            int s0 = __shfl_sync(F, s, j     + half);
            int s1 = __shfl_sync(F, s, j + 2 + half);
            int s2 = __shfl_sync(F, s, j + 4 + half);
            int s3 = __shfl_sync(F, s, j + 6 + half);
            uint2 r0 = rows[s0 * 16 + hl];
            uint2 r1 = rows[s1 * 16 + hl];
            uint2 r2 = rows[s2 * 16 + hl];
            uint2 r3 = rows[s3 * 16 + hl];
            addrow(r0); addrow(r1); addrow(r2); addrow(r3);
        }
        for (; j + 2 <= m; j += 2) {             // single edge-pair
            int sj = __shfl_sync(F, s, j + half);
            addrow(rows[sj * 16 + hl]);
        }
        if (j < m) {                             // odd tail: half 0 only
            int sj = __shfl_sync(F, s, j);
            uint2 r = rows[sj * 16 + hl];
            if (half == 0) addrow(r);
        }
    }
    if (deg > CAP) {   // essentially never: scan overflow list inline
        int n = g_novf;
        if (n > OVF_CAP) n = OVF_CAP;
        for (int e = 0; e < n; e++) {
            int2 ed = g_ovf[e];
            if (ed.y == v && half == 0) addrow(rows[ed.x * 16 + hl]);
        }
    }

    // fold the two half-warps: lane l and lane l+16 hold the same 4 dims
    acc.x += __shfl_xor_sync(F, acc.x, 16);
    acc.y += __shfl_xor_sync(F, acc.y, 16);
    acc.z += __shfl_xor_sync(F, acc.z, 16);
    acc.w += __shfl_xor_sync(F, acc.w, 16);

    acc.x *= dv; acc.y *= dv; acc.z *= dv; acc.w *= dv;

    if (half == 0) {
        if (TO_POOL) {
            int g = batch[v];
            if ((unsigned)g < N_GRAPHS) {
                float* p = &g_pool[g * 64 + hl * 4];
                atomicAdd(p + 0, acc.x);
                atomicAdd(p + 1, acc.y);
                atomicAdd(p + 2, acc.z);
                atomicAdd(p + 3, acc.w);
            }
            if (lane == 0) g_cnt[v] = 0;   // self-clean for next call
        } else {
            float4 b = *(const float4*)&bias[hl * 4];
            __half2 o0 = __floats2half2_rn(acc.x + b.x, acc.y + b.y);
            __half2 o1 = __floats2half2_rn(acc.z + b.z, acc.w + b.w);
            uint2 pack;
            pack.x = *reinterpret_cast<uint32_t*>(&o0);
            pack.y = *reinterpret_cast<uint32_t*>(&o1);
            ((uint2*)g_h_h)[v * 16 + hl] = pack;
        }
    }
}

// -------- head: mean = pool/cnt + b2; relu(mean@W3+b3) @ W4 + b4 ----------
// Also self-cleans g_pool / g_gcnt / g_novf for the next call.
__global__ void k_head(const float* __restrict__ b2,
                       const float* __restrict__ W3, const float* __restrict__ b3,
                       const float* __restrict__ W4, const float* __restrict__ b4,
                       float* __restrict__ out) {
    int g = blockIdx.x;
    int j = threadIdx.x;
    __shared__ float mean[64];
    __shared__ float t[64];
    float c = (float)max(g_gcnt[g], 1);
    mean[j] = g_pool[g * 64 + j] / c + b2[j];
    g_pool[g * 64 + j] = 0.f;              // self-clean
    __syncthreads();
    if (j == 0) g_gcnt[g] = 0;             // self-clean (after all reads)
    if (g == 0 && j == 0) g_novf = 0;      // self-clean
    float acc = 0.f;
    #pragma unroll
    for (int k = 0; k < 64; k++) acc += mean[k] * W3[k * 64 + j];
    t[j] = fmaxf(acc + b3[j], 0.f) * W4[j];
    __syncthreads();
    if (j < 32) {
        float v = t[j] + t[j + 32];
        #pragma unroll
        for (int s = 16; s > 0; s >>= 1) v += __shfl_down_sync(0xffffffffu, v, s);
        if (j == 0) out[g] = v + b4[0];
    }
}

extern "C" void kernel_launch(void* const* d_in, const int* in_sizes, int n_in,
                              void* d_out, int out_size) {
    const float* x     = (const float*)d_in[0];
    const int*   ei    = (const int*)d_in[1];
    const int*   batch = (const int*)d_in[2];
    const float* W1    = (const float*)d_in[3];
    const float* b1    = (const float*)d_in[4];
    const float* W2    = (const float*)d_in[5];
    const float* b2    = (const float*)d_in[6];
    const float* W3    = (const float*)d_in[7];
    const float* b3    = (const float*)d_in[8];
    const float* W4    = (const float*)d_in[9];
    const float* b4    = (const float*)d_in[10];
    float* out = (float*)d_out;

    const int SMEM_F32 = 2 * (128 * 72 * 4) + 64 * 72 * 2;
    const int SMEM_F16 = 2 * (128 * 80 * 2) + 64 * 72 * 2;
    static bool attr_done = false;
    if (!attr_done) {
        cudaFuncSetAttribute(k_gemm<false>,
                             cudaFuncAttributeMaxDynamicSharedMemorySize, SMEM_F32);
        cudaFuncSetAttribute(k_gemm<true>,
                             cudaFuncAttributeMaxDynamicSharedMemorySize, SMEM_F16);
        attr_done = true;
    }

    const int GEMM_GRID = 296;
    const int AGG_BLOCKS = (N_NODES * 32 + 255) / 256;

    k_build<<<(N_EDGES / 4 + 255) / 256, 256>>>(ei);
    k_dinv<<<(N_NODES + 255) / 256, 256>>>(batch);

    k_gemm<false><<<GEMM_GRID, 256, SMEM_F32>>>(x, W1);
    k_agg<false><<<AGG_BLOCKS, 256>>>(b1, batch);

    k_gemm<true><<<GEMM_GRID, 256, SMEM_F16>>>(nullptr, W2);
    k_agg<true><<<AGG_BLOCKS, 256>>>(nullptr, batch);

    k_head<<<N_GRAPHS, 64>>>(b2, W3, b3, W4, b4, out);
}

// round 15
// speedup vs baseline: 1.2774x; 1.2774x over previous
#include <cuda_runtime.h>
#include <cuda_bf16.h>
#include <cuda_fp16.h>
#include <cstdint>

#define N_NODES 100000
#define N_EDGES 1600000
#define N_GRAPHS 512
#define CAP 64
#define OVF_CAP 8192

// -------- persistent device state (self-cleaning across calls; .bss zero) --
__device__ int     g_cnt[N_NODES];          // zeroed by agg2 of previous call
__device__ int     g_col[N_NODES * CAP];
__device__ float   g_dinv[N_NODES];
__device__ __half2 g_tmp_h[N_NODES * 32];   // gemm rows, prescaled by dinv[row]
__device__ __half2 g_h_h[N_NODES * 32];     // layer-1 agg output (+b1), fp16
__device__ float   g_pool[N_GRAPHS * 64];   // zeroed by k_head
__device__ int     g_gcnt[N_GRAPHS];        // zeroed by k_head
__device__ int     g_novf;                  // zeroed by k_head
__device__ int2    g_ovf[OVF_CAP];

__device__ __forceinline__ void cp_async16(uint32_t daddr, const void* src, int nbytes) {
    asm volatile("cp.async.ca.shared.global [%0], [%1], 16, %2;"
                 :: "r"(daddr), "l"(src), "r"(nbytes));
}

// -------- build ELL adjacency (4 edges/thread) + per-graph node counts ----
__global__ void k_build(const int* __restrict__ ei, const int* __restrict__ batch) {
    int tid = blockIdx.x * blockDim.x + threadIdx.x;
    // folded from k_dinv: per-graph node histogram (grid covers N_NODES)
    if (tid < N_NODES) {
        int g = batch[tid];
        if ((unsigned)g < N_GRAPHS) atomicAdd(&g_gcnt[g], 1);
    }
    int i4 = tid;
    if (i4 >= N_EDGES / 4) return;
    int4 s4 = ((const int4*)ei)[i4];
    int4 d4 = ((const int4*)(ei + N_EDGES))[i4];
    int ss[4] = {s4.x, s4.y, s4.z, s4.w};
    int dd[4] = {d4.x, d4.y, d4.z, d4.w};
    #pragma unroll
    for (int k = 0; k < 4; k++) {
        int src = ss[k], dst = dd[k];
        if ((unsigned)src >= N_NODES || (unsigned)dst >= N_NODES) continue;
        int pos = atomicAdd(&g_cnt[dst], 1);
        if (pos < CAP) {
            g_col[dst * CAP + pos] = src;
        } else {
            int o = atomicAdd(&g_novf, 1);
            if (o < OVF_CAP) g_ovf[o] = make_int2(src, dst);
        }
    }
}

// -------- tensor-core GEMM, persistent + double-buffered cp.async ----------
// Both layers write rows prescaled by dinv[row].
// FROM_H=false: fp32 X @ W1; computes dinv=rsqrt(cnt+1) inline and persists
//               g_dinv (build precedes gemm0, counts are final).
// FROM_H=true : relu(g_h_h fp16) @ W2; reads persisted g_dinv.
template <bool FROM_H>
__global__ void __launch_bounds__(256) k_gemm(const float* __restrict__ X,
                                              const float* __restrict__ W) {
    constexpr int PADH = 80;
    constexpr int PADF = 72;
    constexpr int XBYTES = FROM_H ? (128 * PADH * 2) : (128 * PADF * 4);
    extern __shared__ __align__(16) unsigned char smem[];
    unsigned char* xb0 = smem;
    unsigned char* xb1 = smem + XBYTES;
    __half* Wt = (__half*)(smem + 2 * XBYTES);   // Wt[n][k] = W[k][n], 64x72

    int t = threadIdx.x;
    int lane = t & 31;
    int w = t >> 5;
    const int nt = (N_NODES + 127) / 128;

    auto stage = [&](int tile, unsigned char* buf) {
        uint32_t b = (uint32_t)__cvta_generic_to_shared(buf);
        int row0 = tile * 128;
        if (FROM_H) {
            #pragma unroll 4
            for (int i = t; i < 128 * 8; i += 256) {
                int r = i >> 3, ch = i & 7;
                int row = row0 + r;
                int rc = row < N_NODES ? row : 0;
                cp_async16(b + (uint32_t)(r * PADH + ch * 8) * 2,
                           (const char*)g_h_h + (size_t)rc * 128 + ch * 16,
                           row < N_NODES ? 16 : 0);
            }
        } else {
            #pragma unroll 8
            for (int i = t; i < 128 * 16; i += 256) {
                int r = i >> 4, ch = i & 15;
                int row = row0 + r;
                int rc = row < N_NODES ? row : 0;
                cp_async16(b + (uint32_t)(r * PADF + ch * 4) * 4,
                           (const char*)X + (size_t)rc * 256 + ch * 16,
                           row < N_NODES ? 16 : 0);
            }
        }
    };

    int tile = blockIdx.x;
    if (tile < nt) stage(tile, xb0);
    for (int i = t; i < 64 * 64; i += 256) {
        int k = i >> 6, n = i & 63;
        Wt[n * 72 + k] = __float2half_rn(W[i]);
    }
    asm volatile("cp.async.commit_group;");

    int grp = lane >> 2;
    int qid = lane & 3;
    int arow = w * 16 + grp;
    const __half2 z2 = __float2half2_rn(0.f);

    int buf = 0;
    for (; tile < nt; tile += gridDim.x) {
        int nxt = tile + gridDim.x;
        if (nxt < nt) {
            stage(nxt, buf ? xb0 : xb1);
            asm volatile("cp.async.commit_group;");
            asm volatile("cp.async.wait_group 1;");
        } else {
            asm volatile("cp.async.wait_group 0;");
        }
        __syncthreads();

        const unsigned char* xcur = buf ? xb1 : xb0;
        const __half* Xh = (const __half*)xcur;
        const float*  Xf = (const float*)xcur;

        float c[8][4];
        #pragma unroll
        for (int n = 0; n < 8; n++)
            #pragma unroll
            for (int j = 0; j < 4; j++) c[n][j] = 0.f;

        #pragma unroll
        for (int kk = 0; kk < 4; kk++) {
            int k0 = kk * 16 + qid * 2;
            uint32_t a0, a1, a2, a3;
            if (FROM_H) {
                __half2 v0 = __hmax2(*(const __half2*)&Xh[(arow)     * PADH + k0], z2);
                __half2 v1 = __hmax2(*(const __half2*)&Xh[(arow + 8) * PADH + k0], z2);
                __half2 v2 = __hmax2(*(const __half2*)&Xh[(arow)     * PADH + k0 + 8], z2);
                __half2 v3 = __hmax2(*(const __half2*)&Xh[(arow + 8) * PADH + k0 + 8], z2);
                a0 = *reinterpret_cast<uint32_t*>(&v0);
                a1 = *reinterpret_cast<uint32_t*>(&v1);
                a2 = *reinterpret_cast<uint32_t*>(&v2);
                a3 = *reinterpret_cast<uint32_t*>(&v3);
            } else {
                float2 f0 = *(const float2*)&Xf[(arow)     * PADF + k0];
                float2 f1 = *(const float2*)&Xf[(arow + 8) * PADF + k0];
                float2 f2 = *(const float2*)&Xf[(arow)     * PADF + k0 + 8];
                float2 f3 = *(const float2*)&Xf[(arow + 8) * PADF + k0 + 8];
                __half2 v0 = __floats2half2_rn(f0.x, f0.y);
                __half2 v1 = __floats2half2_rn(f1.x, f1.y);
                __half2 v2 = __floats2half2_rn(f2.x, f2.y);
                __half2 v3 = __floats2half2_rn(f3.x, f3.y);
                a0 = *reinterpret_cast<uint32_t*>(&v0);
                a1 = *reinterpret_cast<uint32_t*>(&v1);
                a2 = *reinterpret_cast<uint32_t*>(&v2);
                a3 = *reinterpret_cast<uint32_t*>(&v3);
            }
            #pragma unroll
            for (int n = 0; n < 8; n++) {
                int nc = n * 8 + grp;
                uint32_t b0 = *(const uint32_t*)&Wt[nc * 72 + k0];
                uint32_t b1 = *(const uint32_t*)&Wt[nc * 72 + k0 + 8];
                asm volatile(
                    "mma.sync.aligned.m16n8k16.row.col.f32.f16.f16.f32 "
                    "{%0,%1,%2,%3}, {%4,%5,%6,%7}, {%8,%9}, {%0,%1,%2,%3};"
                    : "+f"(c[n][0]), "+f"(c[n][1]), "+f"(c[n][2]), "+f"(c[n][3])
                    : "r"(a0), "r"(a1), "r"(a2), "r"(a3), "r"(b0), "r"(b1));
            }
        }

        int r0 = tile * 128 + w * 16 + grp;
        int r1 = r0 + 8;
        float dv0, dv1;
        if (FROM_H) {
            dv0 = (r0 < N_NODES) ? g_dinv[r0] : 0.f;
            dv1 = (r1 < N_NODES) ? g_dinv[r1] : 0.f;
        } else {
            // dinv computed inline from final counts; persist for agg/gemm1
            dv0 = (r0 < N_NODES) ? rsqrtf((float)(g_cnt[r0] + 1)) : 0.f;
            dv1 = (r1 < N_NODES) ? rsqrtf((float)(g_cnt[r1] + 1)) : 0.f;
            if (qid == 0) {
                if (r0 < N_NODES) g_dinv[r0] = dv0;
                if (r1 < N_NODES) g_dinv[r1] = dv1;
            }
        }
        #pragma unroll
        for (int n = 0; n < 8; n++) {
            int cw = n * 4 + qid;
            if (r0 < N_NODES)
                g_tmp_h[r0 * 32 + cw] = __floats2half2_rn(c[n][0] * dv0, c[n][1] * dv0);
            if (r1 < N_NODES)
                g_tmp_h[r1 * 32 + cw] = __floats2half2_rn(c[n][2] * dv1, c[n][3] * dv1);
        }
        __syncthreads();
        buf ^= 1;
    }
}

// -------- aggregation: warp per dst; rows pre-scaled; inline overflow ------
// (byte-identical to the proven R13 kernel)
template <bool TO_POOL>
__global__ void __launch_bounds__(256) k_agg(const float* __restrict__ bias,
                                             const int* __restrict__ batch) {
    int warp = (blockIdx.x * blockDim.x + threadIdx.x) >> 5;
    int lane = threadIdx.x & 31;
    if (warp >= N_NODES) return;
    int v = warp;
    float dv = g_dinv[v];

    float2 accn = __half22float2(g_tmp_h[v * 32 + lane]);  // self (prescaled)
    int deg = g_cnt[v];
    int degc = deg > CAP ? CAP : deg;
    const int* cols = &g_col[v * CAP];
    for (int base = 0; base < degc; base += 32) {
        int s = (base + lane < degc) ? cols[base + lane] : 0;
        int m = min(32, degc - base);
        int j = 0;
        for (; j + 4 <= m; j += 4) {
            int s0 = __shfl_sync(0xffffffffu, s, j);
            int s1 = __shfl_sync(0xffffffffu, s, j + 1);
            int s2 = __shfl_sync(0xffffffffu, s, j + 2);
            int s3 = __shfl_sync(0xffffffffu, s, j + 3);
            float2 f0 = __half22float2(g_tmp_h[s0 * 32 + lane]);
            float2 f1 = __half22float2(g_tmp_h[s1 * 32 + lane]);
            float2 f2 = __half22float2(g_tmp_h[s2 * 32 + lane]);
            float2 f3 = __half22float2(g_tmp_h[s3 * 32 + lane]);
            accn.x += (f0.x + f1.x) + (f2.x + f3.x);
            accn.y += (f0.y + f1.y) + (f2.y + f3.y);
        }
        for (; j < m; j++) {
            int sj = __shfl_sync(0xffffffffu, s, j);
            float2 f = __half22float2(g_tmp_h[sj * 32 + lane]);
            accn.x += f.x;
            accn.y += f.y;
        }
    }
    if (deg > CAP) {   // essentially never: scan overflow list inline
        int n = g_novf;
        if (n > OVF_CAP) n = OVF_CAP;
        for (int e = 0; e < n; e++) {
            int2 ed = g_ovf[e];
            if (ed.y == v) {
                float2 f = __half22float2(g_tmp_h[ed.x * 32 + lane]);
                accn.x += f.x;
                accn.y += f.y;
            }
        }
    }

    float2 acc;
    acc.x = dv * accn.x;
    acc.y = dv * accn.y;

    if (TO_POOL) {
        int g = batch[v];
        if ((unsigned)g < N_GRAPHS) {
            atomicAdd(&g_pool[g * 64 + lane * 2], acc.x);
            atomicAdd(&g_pool[g * 64 + lane * 2 + 1], acc.y);
        }
        if (lane == 0) g_cnt[v] = 0;   // self-clean for next call
    } else {
        float2 b = *(const float2*)&bias[lane * 2];
        g_h_h[v * 32 + lane] = __floats2half2_rn(acc.x + b.x, acc.y + b.y);
    }
}

// -------- head: mean = pool/cnt + b2; relu(mean@W3+b3) @ W4 + b4 ----------
// Also self-cleans g_pool / g_gcnt / g_novf for the next call.
__global__ void k_head(const float* __restrict__ b2,
                       const float* __restrict__ W3, const float* __restrict__ b3,
                       const float* __restrict__ W4, const float* __restrict__ b4,
                       float* __restrict__ out) {
    int g = blockIdx.x;
    int j = threadIdx.x;
    __shared__ float mean[64];
    __shared__ float t[64];
    float c = (float)max(g_gcnt[g], 1);
    mean[j] = g_pool[g * 64 + j] / c + b2[j];
    g_pool[g * 64 + j] = 0.f;              // self-clean
    __syncthreads();
    if (j == 0) g_gcnt[g] = 0;             // self-clean (after all reads)
    if (g == 0 && j == 0) g_novf = 0;      // self-clean
    float acc = 0.f;
    #pragma unroll
    for (int k = 0; k < 64; k++) acc += mean[k] * W3[k * 64 + j];
    t[j] = fmaxf(acc + b3[j], 0.f) * W4[j];
    __syncthreads();
    if (j < 32) {
        float v = t[j] + t[j + 32];
        #pragma unroll
        for (int s = 16; s > 0; s >>= 1) v += __shfl_down_sync(0xffffffffu, v, s);
        if (j == 0) out[g] = v + b4[0];
    }
}

extern "C" void kernel_launch(void* const* d_in, const int* in_sizes, int n_in,
                              void* d_out, int out_size) {
    const float* x     = (const float*)d_in[0];
    const int*   ei    = (const int*)d_in[1];
    const int*   batch = (const int*)d_in[2];
    const float* W1    = (const float*)d_in[3];
    const float* b1    = (const float*)d_in[4];
    const float* W2    = (const float*)d_in[5];
    const float* b2    = (const float*)d_in[6];
    const float* W3    = (const float*)d_in[7];
    const float* b3    = (const float*)d_in[8];
    const float* W4    = (const float*)d_in[9];
    const float* b4    = (const float*)d_in[10];
    float* out = (float*)d_out;

    const int SMEM_F32 = 2 * (128 * 72 * 4) + 64 * 72 * 2;
    const int SMEM_F16 = 2 * (128 * 80 * 2) + 64 * 72 * 2;
    static bool attr_done = false;
    if (!attr_done) {
        cudaFuncSetAttribute(k_gemm<false>,
                             cudaFuncAttributeMaxDynamicSharedMemorySize, SMEM_F32);
        cudaFuncSetAttribute(k_gemm<true>,
                             cudaFuncAttributeMaxDynamicSharedMemorySize, SMEM_F16);
        attr_done = true;
    }

    const int GEMM_GRID = 296;
    const int AGG_BLOCKS = (N_NODES * 32 + 255) / 256;

    // 6 nodes, strictly serial.
    k_build<<<(N_EDGES / 4 + 255) / 256, 256>>>(ei, batch);

    k_gemm<false><<<GEMM_GRID, 256, SMEM_F32>>>(x, W1);   // also computes dinv
    k_agg<false><<<AGG_BLOCKS, 256>>>(b1, batch);

    k_gemm<true><<<GEMM_GRID, 256, SMEM_F16>>>(nullptr, W2);
    k_agg<true><<<AGG_BLOCKS, 256>>>(nullptr, batch);

    k_head<<<N_GRAPHS, 64>>>(b2, W3, b3, W4, b4, out);
}

// round 16
// speedup vs baseline: 1.3143x; 1.0289x over previous
#include <cuda_runtime.h>
#include <cuda_bf16.h>
#include <cuda_fp16.h>
#include <cstdint>

#define N_NODES 100000
#define N_EDGES 1600000
#define N_GRAPHS 512
#define CAP 64
#define OVF_CAP 8192

// -------- persistent device state (self-cleaning across calls; .bss zero) --
__device__ int     g_cnt[N_NODES];          // zeroed by agg2 of previous call
__device__ int     g_col[N_NODES * CAP];
__device__ float   g_dinv[N_NODES];
__device__ __half2 g_tmp_h[N_NODES * 32];   // gemm rows, prescaled by dinv[row]
__device__ __half2 g_h_h[N_NODES * 32];     // layer-1 agg output (+b1), fp16
__device__ float   g_pool[N_GRAPHS * 64];   // zeroed by k_head
__device__ int     g_gcnt[N_GRAPHS];        // zeroed by k_head
__device__ int     g_novf;                  // zeroed by k_head
__device__ int2    g_ovf[OVF_CAP];

__device__ __forceinline__ void cp_async16(uint32_t daddr, const void* src, int nbytes) {
    asm volatile("cp.async.ca.shared.global [%0], [%1], 16, %2;"
                 :: "r"(daddr), "l"(src), "r"(nbytes));
}

// -------- build ELL adjacency (4 edges/thread) + per-graph node counts ----
__global__ void k_build(const int* __restrict__ ei, const int* __restrict__ batch) {
    int tid = blockIdx.x * blockDim.x + threadIdx.x;
    if (tid < N_NODES) {
        int g = batch[tid];
        if ((unsigned)g < N_GRAPHS) atomicAdd(&g_gcnt[g], 1);
    }
    int i4 = tid;
    if (i4 >= N_EDGES / 4) return;
    int4 s4 = ((const int4*)ei)[i4];
    int4 d4 = ((const int4*)(ei + N_EDGES))[i4];
    int ss[4] = {s4.x, s4.y, s4.z, s4.w};
    int dd[4] = {d4.x, d4.y, d4.z, d4.w};
    #pragma unroll
    for (int k = 0; k < 4; k++) {
        int src = ss[k], dst = dd[k];
        if ((unsigned)src >= N_NODES || (unsigned)dst >= N_NODES) continue;
        int pos = atomicAdd(&g_cnt[dst], 1);
        if (pos < CAP) {
            g_col[dst * CAP + pos] = src;
        } else {
            int o = atomicAdd(&g_novf, 1);
            if (o < OVF_CAP) g_ovf[o] = make_int2(src, dst);
        }
    }
}

// -------- tensor-core GEMM, persistent + double-buffered cp.async ----------
// FROM_H=false: fp32 X @ W1; computes dinv inline and persists g_dinv.
// FROM_H=true : relu(g_h_h fp16) @ W2; reads persisted g_dinv.
template <bool FROM_H>
__global__ void __launch_bounds__(256) k_gemm(const float* __restrict__ X,
                                              const float* __restrict__ W) {
    constexpr int PADH = 80;
    constexpr int PADF = 72;
    constexpr int XBYTES = FROM_H ? (128 * PADH * 2) : (128 * PADF * 4);
    extern __shared__ __align__(16) unsigned char smem[];
    unsigned char* xb0 = smem;
    unsigned char* xb1 = smem + XBYTES;
    __half* Wt = (__half*)(smem + 2 * XBYTES);   // Wt[n][k] = W[k][n], 64x72

    int t = threadIdx.x;
    int lane = t & 31;
    int w = t >> 5;
    const int nt = (N_NODES + 127) / 128;

    auto stage = [&](int tile, unsigned char* buf) {
        uint32_t b = (uint32_t)__cvta_generic_to_shared(buf);
        int row0 = tile * 128;
        if (FROM_H) {
            #pragma unroll 4
            for (int i = t; i < 128 * 8; i += 256) {
                int r = i >> 3, ch = i & 7;
                int row = row0 + r;
                int rc = row < N_NODES ? row : 0;
                cp_async16(b + (uint32_t)(r * PADH + ch * 8) * 2,
                           (const char*)g_h_h + (size_t)rc * 128 + ch * 16,
                           row < N_NODES ? 16 : 0);
            }
        } else {
            #pragma unroll 8
            for (int i = t; i < 128 * 16; i += 256) {
                int r = i >> 4, ch = i & 15;
                int row = row0 + r;
                int rc = row < N_NODES ? row : 0;
                cp_async16(b + (uint32_t)(r * PADF + ch * 4) * 4,
                           (const char*)X + (size_t)rc * 256 + ch * 16,
                           row < N_NODES ? 16 : 0);
            }
        }
    };

    int tile = blockIdx.x;
    if (tile < nt) stage(tile, xb0);
    for (int i = t; i < 64 * 64; i += 256) {
        int k = i >> 6, n = i & 63;
        Wt[n * 72 + k] = __float2half_rn(W[i]);
    }
    asm volatile("cp.async.commit_group;");

    int grp = lane >> 2;
    int qid = lane & 3;
    int arow = w * 16 + grp;
    const __half2 z2 = __float2half2_rn(0.f);

    int buf = 0;
    for (; tile < nt; tile += gridDim.x) {
        int nxt = tile + gridDim.x;
        if (nxt < nt) {
            stage(nxt, buf ? xb0 : xb1);
            asm volatile("cp.async.commit_group;");
            asm volatile("cp.async.wait_group 1;");
        } else {
            asm volatile("cp.async.wait_group 0;");
        }
        __syncthreads();

        const unsigned char* xcur = buf ? xb1 : xb0;
        const __half* Xh = (const __half*)xcur;
        const float*  Xf = (const float*)xcur;

        float c[8][4];
        #pragma unroll
        for (int n = 0; n < 8; n++)
            #pragma unroll
            for (int j = 0; j < 4; j++) c[n][j] = 0.f;

        #pragma unroll
        for (int kk = 0; kk < 4; kk++) {
            int k0 = kk * 16 + qid * 2;
            uint32_t a0, a1, a2, a3;
            if (FROM_H) {
                __half2 v0 = __hmax2(*(const __half2*)&Xh[(arow)     * PADH + k0], z2);
                __half2 v1 = __hmax2(*(const __half2*)&Xh[(arow + 8) * PADH + k0], z2);
                __half2 v2 = __hmax2(*(const __half2*)&Xh[(arow)     * PADH + k0 + 8], z2);
                __half2 v3 = __hmax2(*(const __half2*)&Xh[(arow + 8) * PADH + k0 + 8], z2);
                a0 = *reinterpret_cast<uint32_t*>(&v0);
                a1 = *reinterpret_cast<uint32_t*>(&v1);
                a2 = *reinterpret_cast<uint32_t*>(&v2);
                a3 = *reinterpret_cast<uint32_t*>(&v3);
            } else {
                float2 f0 = *(const float2*)&Xf[(arow)     * PADF + k0];
                float2 f1 = *(const float2*)&Xf[(arow + 8) * PADF + k0];
                float2 f2 = *(const float2*)&Xf[(arow)     * PADF + k0 + 8];
                float2 f3 = *(const float2*)&Xf[(arow + 8) * PADF + k0 + 8];
                __half2 v0 = __floats2half2_rn(f0.x, f0.y);
                __half2 v1 = __floats2half2_rn(f1.x, f1.y);
                __half2 v2 = __floats2half2_rn(f2.x, f2.y);
                __half2 v3 = __floats2half2_rn(f3.x, f3.y);
                a0 = *reinterpret_cast<uint32_t*>(&v0);
                a1 = *reinterpret_cast<uint32_t*>(&v1);
                a2 = *reinterpret_cast<uint32_t*>(&v2);
                a3 = *reinterpret_cast<uint32_t*>(&v3);
            }
            #pragma unroll
            for (int n = 0; n < 8; n++) {
                int nc = n * 8 + grp;
                uint32_t b0 = *(const uint32_t*)&Wt[nc * 72 + k0];
                uint32_t b1 = *(const uint32_t*)&Wt[nc * 72 + k0 + 8];
                asm volatile(
                    "mma.sync.aligned.m16n8k16.row.col.f32.f16.f16.f32 "
                    "{%0,%1,%2,%3}, {%4,%5,%6,%7}, {%8,%9}, {%0,%1,%2,%3};"
                    : "+f"(c[n][0]), "+f"(c[n][1]), "+f"(c[n][2]), "+f"(c[n][3])
                    : "r"(a0), "r"(a1), "r"(a2), "r"(a3), "r"(b0), "r"(b1));
            }
        }

        int r0 = tile * 128 + w * 16 + grp;
        int r1 = r0 + 8;
        float dv0, dv1;
        if (FROM_H) {
            dv0 = (r0 < N_NODES) ? g_dinv[r0] : 0.f;
            dv1 = (r1 < N_NODES) ? g_dinv[r1] : 0.f;
        } else {
            dv0 = (r0 < N_NODES) ? rsqrtf((float)(g_cnt[r0] + 1)) : 0.f;
            dv1 = (r1 < N_NODES) ? rsqrtf((float)(g_cnt[r1] + 1)) : 0.f;
            if (qid == 0) {
                if (r0 < N_NODES) g_dinv[r0] = dv0;
                if (r1 < N_NODES) g_dinv[r1] = dv1;
            }
        }
        #pragma unroll
        for (int n = 0; n < 8; n++) {
            int cw = n * 4 + qid;
            if (r0 < N_NODES)
                g_tmp_h[r0 * 32 + cw] = __floats2half2_rn(c[n][0] * dv0, c[n][1] * dv0);
            if (r1 < N_NODES)
                g_tmp_h[r1 * 32 + cw] = __floats2half2_rn(c[n][2] * dv1, c[n][3] * dv1);
        }
        __syncthreads();
        buf ^= 1;
    }
}

// -------- aggregation: warp per dst; fp16 pairwise pre-reduction -----------
// Adjacent edge rows are summed once in fp16 (__hadd2) before fp32 convert —
// cuts CVT+FADD issue ~30% in the dominant loop; adds one ~5e-4 rounding/pair.
template <bool TO_POOL>
__global__ void __launch_bounds__(256) k_agg(const float* __restrict__ bias,
                                             const int* __restrict__ batch) {
    int warp = (blockIdx.x * blockDim.x + threadIdx.x) >> 5;
    int lane = threadIdx.x & 31;
    if (warp >= N_NODES) return;
    int v = warp;
    float dv = g_dinv[v];

    float2 accn = __half22float2(g_tmp_h[v * 32 + lane]);  // self (prescaled)
    int deg = g_cnt[v];
    int degc = deg > CAP ? CAP : deg;
    const int* cols = &g_col[v * CAP];
    for (int base = 0; base < degc; base += 32) {
        int s = (base + lane < degc) ? cols[base + lane] : 0;
        int m = min(32, degc - base);
        int j = 0;
        for (; j + 4 <= m; j += 4) {
            int s0 = __shfl_sync(0xffffffffu, s, j);
            int s1 = __shfl_sync(0xffffffffu, s, j + 1);
            int s2 = __shfl_sync(0xffffffffu, s, j + 2);
            int s3 = __shfl_sync(0xffffffffu, s, j + 3);
            __half2 h0 = g_tmp_h[s0 * 32 + lane];
            __half2 h1 = g_tmp_h[s1 * 32 + lane];
            __half2 h2 = g_tmp_h[s2 * 32 + lane];
            __half2 h3 = g_tmp_h[s3 * 32 + lane];
            __half2 p01 = __hadd2(h0, h1);          // fp16 pairwise pre-sum
            __half2 p23 = __hadd2(h2, h3);
            float2 f01 = __half22float2(p01);
            float2 f23 = __half22float2(p23);
            accn.x += f01.x + f23.x;
            accn.y += f01.y + f23.y;
        }
        if (j + 2 <= m) {
            int s0 = __shfl_sync(0xffffffffu, s, j);
            int s1 = __shfl_sync(0xffffffffu, s, j + 1);
            __half2 p = __hadd2(g_tmp_h[s0 * 32 + lane], g_tmp_h[s1 * 32 + lane]);
            float2 f = __half22float2(p);
            accn.x += f.x;
            accn.y += f.y;
            j += 2;
        }
        if (j < m) {
            int sj = __shfl_sync(0xffffffffu, s, j);
            float2 f = __half22float2(g_tmp_h[sj * 32 + lane]);
            accn.x += f.x;
            accn.y += f.y;
        }
    }
    if (deg > CAP) {   // essentially never: scan overflow list inline
        int n = g_novf;
        if (n > OVF_CAP) n = OVF_CAP;
        for (int e = 0; e < n; e++) {
            int2 ed = g_ovf[e];
            if (ed.y == v) {
                float2 f = __half22float2(g_tmp_h[ed.x * 32 + lane]);
                accn.x += f.x;
                accn.y += f.y;
            }
        }
    }

    float2 acc;
    acc.x = dv * accn.x;
    acc.y = dv * accn.y;

    if (TO_POOL) {
        int g = batch[v];
        if ((unsigned)g < N_GRAPHS) {
            atomicAdd(&g_pool[g * 64 + lane * 2], acc.x);
            atomicAdd(&g_pool[g * 64 + lane * 2 + 1], acc.y);
        }
        if (lane == 0) g_cnt[v] = 0;   // self-clean for next call
    } else {
        float2 b = *(const float2*)&bias[lane * 2];
        g_h_h[v * 32 + lane] = __floats2half2_rn(acc.x + b.x, acc.y + b.y);
    }
}

// -------- head: mean = pool/cnt + b2; relu(mean@W3+b3) @ W4 + b4 ----------
__global__ void k_head(const float* __restrict__ b2,
                       const float* __restrict__ W3, const float* __restrict__ b3,
                       const float* __restrict__ W4, const float* __restrict__ b4,
                       float* __restrict__ out) {
    int g = blockIdx.x;
    int j = threadIdx.x;
    __shared__ float mean[64];
    __shared__ float t[64];
    float c = (float)max(g_gcnt[g], 1);
    mean[j] = g_pool[g * 64 + j] / c + b2[j];
    g_pool[g * 64 + j] = 0.f;              // self-clean
    __syncthreads();
    if (j == 0) g_gcnt[g] = 0;             // self-clean (after all reads)
    if (g == 0 && j == 0) g_novf = 0;      // self-clean
    float acc = 0.f;
    #pragma unroll
    for (int k = 0; k < 64; k++) acc += mean[k] * W3[k * 64 + j];
    t[j] = fmaxf(acc + b3[j], 0.f) * W4[j];
    __syncthreads();
    if (j < 32) {
        float v = t[j] + t[j + 32];
        #pragma unroll
        for (int s = 16; s > 0; s >>= 1) v += __shfl_down_sync(0xffffffffu, v, s);
        if (j == 0) out[g] = v + b4[0];
    }
}

extern "C" void kernel_launch(void* const* d_in, const int* in_sizes, int n_in,
                              void* d_out, int out_size) {
    const float* x     = (const float*)d_in[0];
    const int*   ei    = (const int*)d_in[1];
    const int*   batch = (const int*)d_in[2];
    const float* W1    = (const float*)d_in[3];
    const float* b1    = (const float*)d_in[4];
    const float* W2    = (const float*)d_in[5];
    const float* b2    = (const float*)d_in[6];
    const float* W3    = (const float*)d_in[7];
    const float* b3    = (const float*)d_in[8];
    const float* W4    = (const float*)d_in[9];
    const float* b4    = (const float*)d_in[10];
    float* out = (float*)d_out;

    const int SMEM_F32 = 2 * (128 * 72 * 4) + 64 * 72 * 2;   // 82,944 B
    const int SMEM_F16 = 2 * (128 * 80 * 2) + 64 * 72 * 2;   // 50,176 B
    static bool attr_done = false;
    if (!attr_done) {
        cudaFuncSetAttribute(k_gemm<false>,
                             cudaFuncAttributeMaxDynamicSharedMemorySize, SMEM_F32);
        cudaFuncSetAttribute(k_gemm<true>,
                             cudaFuncAttributeMaxDynamicSharedMemorySize, SMEM_F16);
        attr_done = true;
    }

    const int GEMM0_GRID = 296;   // 2 blocks/SM (83KB smem each)
    const int GEMM1_GRID = 592;   // 4 blocks/SM (50KB smem each) — latency hiding
    const int AGG_BLOCKS = (N_NODES * 32 + 255) / 256;

    // 6 nodes, strictly serial.
    k_build<<<(N_EDGES / 4 + 255) / 256, 256>>>(ei, batch);

    k_gemm<false><<<GEMM0_GRID, 256, SMEM_F32>>>(x, W1);   // also computes dinv
    k_agg<false><<<AGG_BLOCKS, 256>>>(b1, batch);

    k_gemm<true><<<GEMM1_GRID, 256, SMEM_F16>>>(nullptr, W2);
    k_agg<true><<<AGG_BLOCKS, 256>>>(nullptr, batch);

    k_head<<<N_GRAPHS, 64>>>(b2, W3, b3, W4, b4, out);
}

// round 17
// speedup vs baseline: 1.3167x; 1.0018x over previous
#include <cuda_runtime.h>
#include <cuda_bf16.h>
#include <cuda_fp16.h>
#include <cstdint>

#define N_NODES 100000
#define N_EDGES 1600000
#define N_GRAPHS 512
#define CAP 48          // P(deg>48 | Poisson(16)) ~ 1e-11; overflow path exact
#define OVF_CAP 8192

// -------- persistent device state (self-cleaning across calls; .bss zero) --
__device__ int     g_cnt[N_NODES];          // zeroed by agg2 of previous call
__device__ int     g_col[N_NODES * CAP];
__device__ float   g_dinv[N_NODES];
__device__ __half2 g_tmp_h[N_NODES * 32];   // gemm rows, prescaled by dinv[row]
__device__ __half2 g_h_h[N_NODES * 32];     // layer-1 agg output (+b1), fp16
__device__ float   g_pool[N_GRAPHS * 64];   // zeroed by k_head
__device__ int     g_gcnt[N_GRAPHS];        // zeroed by k_head
__device__ int     g_novf;                  // zeroed by k_head
__device__ int2    g_ovf[OVF_CAP];

__device__ __forceinline__ void cp_async16(uint32_t daddr, const void* src, int nbytes) {
    asm volatile("cp.async.ca.shared.global [%0], [%1], 16, %2;"
                 :: "r"(daddr), "l"(src), "r"(nbytes));
}

// -------- build ELL adjacency (8 edges/thread, 8 MLP chains) + graph counts
__global__ void k_build(const int* __restrict__ ei, const int* __restrict__ batch) {
    int tid = blockIdx.x * blockDim.x + threadIdx.x;
    if (tid < N_NODES) {
        int g = batch[tid];
        if ((unsigned)g < N_GRAPHS) atomicAdd(&g_gcnt[g], 1);
    }
    if (tid >= N_EDGES / 8) return;
    int4 sa = ((const int4*)ei)[tid * 2];
    int4 sb = ((const int4*)ei)[tid * 2 + 1];
    int4 da = ((const int4*)(ei + N_EDGES))[tid * 2];
    int4 db = ((const int4*)(ei + N_EDGES))[tid * 2 + 1];
    int ss[8] = {sa.x, sa.y, sa.z, sa.w, sb.x, sb.y, sb.z, sb.w};
    int dd[8] = {da.x, da.y, da.z, da.w, db.x, db.y, db.z, db.w};
    #pragma unroll
    for (int k = 0; k < 8; k++) {
        int src = ss[k], dst = dd[k];
        if ((unsigned)src >= N_NODES || (unsigned)dst >= N_NODES) continue;
        int pos = atomicAdd(&g_cnt[dst], 1);
        if (pos < CAP) {
            g_col[dst * CAP + pos] = src;
        } else {
            int o = atomicAdd(&g_novf, 1);
            if (o < OVF_CAP) g_ovf[o] = make_int2(src, dst);
        }
    }
}

// -------- tensor-core GEMM, persistent + double-buffered cp.async ----------
// FROM_H=false: fp32 X @ W1; computes dinv inline and persists g_dinv.
// FROM_H=true : relu(g_h_h fp16) @ W2; reads persisted g_dinv.
template <bool FROM_H>
__global__ void __launch_bounds__(256) k_gemm(const float* __restrict__ X,
                                              const float* __restrict__ W) {
    constexpr int PADH = 80;
    constexpr int PADF = 72;
    constexpr int XBYTES = FROM_H ? (128 * PADH * 2) : (128 * PADF * 4);
    extern __shared__ __align__(16) unsigned char smem[];
    unsigned char* xb0 = smem;
    unsigned char* xb1 = smem + XBYTES;
    __half* Wt = (__half*)(smem + 2 * XBYTES);   // Wt[n][k] = W[k][n], 64x72

    int t = threadIdx.x;
    int lane = t & 31;
    int w = t >> 5;
    const int nt = (N_NODES + 127) / 128;

    auto stage = [&](int tile, unsigned char* buf) {
        uint32_t b = (uint32_t)__cvta_generic_to_shared(buf);
        int row0 = tile * 128;
        if (FROM_H) {
            #pragma unroll 4
            for (int i = t; i < 128 * 8; i += 256) {
                int r = i >> 3, ch = i & 7;
                int row = row0 + r;
                int rc = row < N_NODES ? row : 0;
                cp_async16(b + (uint32_t)(r * PADH + ch * 8) * 2,
                           (const char*)g_h_h + (size_t)rc * 128 + ch * 16,
                           row < N_NODES ? 16 : 0);
            }
        } else {
            #pragma unroll 8
            for (int i = t; i < 128 * 16; i += 256) {
                int r = i >> 4, ch = i & 15;
                int row = row0 + r;
                int rc = row < N_NODES ? row : 0;
                cp_async16(b + (uint32_t)(r * PADF + ch * 4) * 4,
                           (const char*)X + (size_t)rc * 256 + ch * 16,
                           row < N_NODES ? 16 : 0);
            }
        }
    };

    int tile = blockIdx.x;
    if (tile < nt) stage(tile, xb0);
    for (int i = t; i < 64 * 64; i += 256) {
        int k = i >> 6, n = i & 63;
        Wt[n * 72 + k] = __float2half_rn(W[i]);
    }
    asm volatile("cp.async.commit_group;");

    int grp = lane >> 2;
    int qid = lane & 3;
    int arow = w * 16 + grp;
    const __half2 z2 = __float2half2_rn(0.f);

    int buf = 0;
    for (; tile < nt; tile += gridDim.x) {
        int nxt = tile + gridDim.x;
        if (nxt < nt) {
            stage(nxt, buf ? xb0 : xb1);
            asm volatile("cp.async.commit_group;");
            asm volatile("cp.async.wait_group 1;");
        } else {
            asm volatile("cp.async.wait_group 0;");
        }
        __syncthreads();

        const unsigned char* xcur = buf ? xb1 : xb0;
        const __half* Xh = (const __half*)xcur;
        const float*  Xf = (const float*)xcur;

        float c[8][4];
        #pragma unroll
        for (int n = 0; n < 8; n++)
            #pragma unroll
            for (int j = 0; j < 4; j++) c[n][j] = 0.f;

        #pragma unroll
        for (int kk = 0; kk < 4; kk++) {
            int k0 = kk * 16 + qid * 2;
            uint32_t a0, a1, a2, a3;
            if (FROM_H) {
                __half2 v0 = __hmax2(*(const __half2*)&Xh[(arow)     * PADH + k0], z2);
                __half2 v1 = __hmax2(*(const __half2*)&Xh[(arow + 8) * PADH + k0], z2);
                __half2 v2 = __hmax2(*(const __half2*)&Xh[(arow)     * PADH + k0 + 8], z2);
                __half2 v3 = __hmax2(*(const __half2*)&Xh[(arow + 8) * PADH + k0 + 8], z2);
                a0 = *reinterpret_cast<uint32_t*>(&v0);
                a1 = *reinterpret_cast<uint32_t*>(&v1);
                a2 = *reinterpret_cast<uint32_t*>(&v2);
                a3 = *reinterpret_cast<uint32_t*>(&v3);
            } else {
                float2 f0 = *(const float2*)&Xf[(arow)     * PADF + k0];
                float2 f1 = *(const float2*)&Xf[(arow + 8) * PADF + k0];
                float2 f2 = *(const float2*)&Xf[(arow)     * PADF + k0 + 8];
                float2 f3 = *(const float2*)&Xf[(arow + 8) * PADF + k0 + 8];
                __half2 v0 = __floats2half2_rn(f0.x, f0.y);
                __half2 v1 = __floats2half2_rn(f1.x, f1.y);
                __half2 v2 = __floats2half2_rn(f2.x, f2.y);
                __half2 v3 = __floats2half2_rn(f3.x, f3.y);
                a0 = *reinterpret_cast<uint32_t*>(&v0);
                a1 = *reinterpret_cast<uint32_t*>(&v1);
                a2 = *reinterpret_cast<uint32_t*>(&v2);
                a3 = *reinterpret_cast<uint32_t*>(&v3);
            }
            #pragma unroll
            for (int n = 0; n < 8; n++) {
                int nc = n * 8 + grp;
                uint32_t b0 = *(const uint32_t*)&Wt[nc * 72 + k0];
                uint32_t b1 = *(const uint32_t*)&Wt[nc * 72 + k0 + 8];
                asm volatile(
                    "mma.sync.aligned.m16n8k16.row.col.f32.f16.f16.f32 "
                    "{%0,%1,%2,%3}, {%4,%5,%6,%7}, {%8,%9}, {%0,%1,%2,%3};"
                    : "+f"(c[n][0]), "+f"(c[n][1]), "+f"(c[n][2]), "+f"(c[n][3])
                    : "r"(a0), "r"(a1), "r"(a2), "r"(a3), "r"(b0), "r"(b1));
            }
        }

        int r0 = tile * 128 + w * 16 + grp;
        int r1 = r0 + 8;
        float dv0, dv1;
        if (FROM_H) {
            dv0 = (r0 < N_NODES) ? g_dinv[r0] : 0.f;
            dv1 = (r1 < N_NODES) ? g_dinv[r1] : 0.f;
        } else {
            dv0 = (r0 < N_NODES) ? rsqrtf((float)(g_cnt[r0] + 1)) : 0.f;
            dv1 = (r1 < N_NODES) ? rsqrtf((float)(g_cnt[r1] + 1)) : 0.f;
            if (qid == 0) {
                if (r0 < N_NODES) g_dinv[r0] = dv0;
                if (r1 < N_NODES) g_dinv[r1] = dv1;
            }
        }
        #pragma unroll
        for (int n = 0; n < 8; n++) {
            int cw = n * 4 + qid;
            if (r0 < N_NODES)
                g_tmp_h[r0 * 32 + cw] = __floats2half2_rn(c[n][0] * dv0, c[n][1] * dv0);
            if (r1 < N_NODES)
                g_tmp_h[r1 * 32 + cw] = __floats2half2_rn(c[n][2] * dv1, c[n][3] * dv1);
        }
        __syncthreads();
        buf ^= 1;
    }
}

// -------- aggregation: warp per dst; fp16 tree pre-reduction ----------------
// Per 4 edges: 3 HADD2 -> 1 convert -> 2 FADD (tree in fp16, fp32 across groups).
template <bool TO_POOL>
__global__ void __launch_bounds__(256) k_agg(const float* __restrict__ bias,
                                             const int* __restrict__ batch) {
    int warp = (blockIdx.x * blockDim.x + threadIdx.x) >> 5;
    int lane = threadIdx.x & 31;
    if (warp >= N_NODES) return;
    int v = warp;
    float dv = g_dinv[v];

    float2 accn = __half22float2(g_tmp_h[v * 32 + lane]);  // self (prescaled)
    int deg = g_cnt[v];
    int degc = deg > CAP ? CAP : deg;
    const int* cols = &g_col[v * CAP];
    for (int base = 0; base < degc; base += 32) {
        int s = (base + lane < degc) ? cols[base + lane] : 0;
        int m = min(32, degc - base);
        int j = 0;
        for (; j + 4 <= m; j += 4) {
            int s0 = __shfl_sync(0xffffffffu, s, j);
            int s1 = __shfl_sync(0xffffffffu, s, j + 1);
            int s2 = __shfl_sync(0xffffffffu, s, j + 2);
            int s3 = __shfl_sync(0xffffffffu, s, j + 3);
            __half2 h0 = g_tmp_h[s0 * 32 + lane];
            __half2 h1 = g_tmp_h[s1 * 32 + lane];
            __half2 h2 = g_tmp_h[s2 * 32 + lane];
            __half2 h3 = g_tmp_h[s3 * 32 + lane];
            __half2 p = __hadd2(__hadd2(h0, h1), __hadd2(h2, h3));  // fp16 tree
            float2 f = __half22float2(p);
            accn.x += f.x;
            accn.y += f.y;
        }
        if (j + 2 <= m) {
            int s0 = __shfl_sync(0xffffffffu, s, j);
            int s1 = __shfl_sync(0xffffffffu, s, j + 1);
            __half2 p = __hadd2(g_tmp_h[s0 * 32 + lane], g_tmp_h[s1 * 32 + lane]);
            float2 f = __half22float2(p);
            accn.x += f.x;
            accn.y += f.y;
            j += 2;
        }
        if (j < m) {
            int sj = __shfl_sync(0xffffffffu, s, j);
            float2 f = __half22float2(g_tmp_h[sj * 32 + lane]);
            accn.x += f.x;
            accn.y += f.y;
        }
    }
    if (deg > CAP) {   // essentially never: scan overflow list inline
        int n = g_novf;
        if (n > OVF_CAP) n = OVF_CAP;
        for (int e = 0; e < n; e++) {
            int2 ed = g_ovf[e];
            if (ed.y == v) {
                float2 f = __half22float2(g_tmp_h[ed.x * 32 + lane]);
                accn.x += f.x;
                accn.y += f.y;
            }
        }
    }

    float2 acc;
    acc.x = dv * accn.x;
    acc.y = dv * accn.y;

    if (TO_POOL) {
        int g = batch[v];
        if ((unsigned)g < N_GRAPHS) {
            atomicAdd(&g_pool[g * 64 + lane * 2], acc.x);
            atomicAdd(&g_pool[g * 64 + lane * 2 + 1], acc.y);
        }
        if (lane == 0) g_cnt[v] = 0;   // self-clean for next call
    } else {
        float2 b = *(const float2*)&bias[lane * 2];
        g_h_h[v * 32 + lane] = __floats2half2_rn(acc.x + b.x, acc.y + b.y);
    }
}

// -------- head: mean = pool/cnt + b2; relu(mean@W3+b3) @ W4 + b4 ----------
__global__ void k_head(const float* __restrict__ b2,
                       const float* __restrict__ W3, const float* __restrict__ b3,
                       const float* __restrict__ W4, const float* __restrict__ b4,
                       float* __restrict__ out) {
    int g = blockIdx.x;
    int j = threadIdx.x;
    __shared__ float mean[64];
    __shared__ float t[64];
    float c = (float)max(g_gcnt[g], 1);
    mean[j] = g_pool[g * 64 + j] / c + b2[j];
    g_pool[g * 64 + j] = 0.f;              // self-clean
    __syncthreads();
    if (j == 0) g_gcnt[g] = 0;             // self-clean (after all reads)
    if (g == 0 && j == 0) g_novf = 0;      // self-clean
    float acc = 0.f;
    #pragma unroll
    for (int k = 0; k < 64; k++) acc += mean[k] * W3[k * 64 + j];
    t[j] = fmaxf(acc + b3[j], 0.f) * W4[j];
    __syncthreads();
    if (j < 32) {
        float v = t[j] + t[j + 32];
        #pragma unroll
        for (int s = 16; s > 0; s >>= 1) v += __shfl_down_sync(0xffffffffu, v, s);
        if (j == 0) out[g] = v + b4[0];
    }
}

extern "C" void kernel_launch(void* const* d_in, const int* in_sizes, int n_in,
                              void* d_out, int out_size) {
    const float* x     = (const float*)d_in[0];
    const int*   ei    = (const int*)d_in[1];
    const int*   batch = (const int*)d_in[2];
    const float* W1    = (const float*)d_in[3];
    const float* b1    = (const float*)d_in[4];
    const float* W2    = (const float*)d_in[5];
    const float* b2    = (const float*)d_in[6];
    const float* W3    = (const float*)d_in[7];
    const float* b3    = (const float*)d_in[8];
    const float* W4    = (const float*)d_in[9];
    const float* b4    = (const float*)d_in[10];
    float* out = (float*)d_out;

    const int SMEM_F32 = 2 * (128 * 72 * 4) + 64 * 72 * 2;   // 82,944 B
    const int SMEM_F16 = 2 * (128 * 80 * 2) + 64 * 72 * 2;   // 50,176 B
    static bool attr_done = false;
    if (!attr_done) {
        cudaFuncSetAttribute(k_gemm<false>,
                             cudaFuncAttributeMaxDynamicSharedMemorySize, SMEM_F32);
        cudaFuncSetAttribute(k_gemm<true>,
                             cudaFuncAttributeMaxDynamicSharedMemorySize, SMEM_F16);
        attr_done = true;
    }

    const int GEMM0_GRID = 296;   // 2 blocks/SM (83KB smem each)
    const int GEMM1_GRID = 592;   // 4 blocks/SM (50KB smem each)
    const int AGG_BLOCKS = (N_NODES * 32 + 255) / 256;

    // 6 nodes, strictly serial.
    k_build<<<(N_EDGES / 8 + 255) / 256, 256>>>(ei, batch);

    k_gemm<false><<<GEMM0_GRID, 256, SMEM_F32>>>(x, W1);   // also computes dinv
    k_agg<false><<<AGG_BLOCKS, 256>>>(b1, batch);

    k_gemm<true><<<GEMM1_GRID, 256, SMEM_F16>>>(nullptr, W2);
    k_agg<true><<<AGG_BLOCKS, 256>>>(nullptr, batch);

    k_head<<<N_GRAPHS, 64>>>(b2, W3, b3, W4, b4, out);
}